// round 13
// baseline (speedup 1.0000x reference)
#include <cuda_runtime.h>
#include <cuda_bf16.h>
#include <cstdint>
#include <cstddef>

// ---------------------------------------------------------------------------
// Problem sizes
// ---------------------------------------------------------------------------
constexpr int NI = 16;      // instances
constexpr int SQ = 2048;    // sequence
constexpr int HH = 1024;    // hidden
constexpr int KE = 8;       // experts
constexpr int DB = 256;     // bottleneck

// ---------------------------------------------------------------------------
// Device scratch (static globals -- no allocations allowed)
// ---------------------------------------------------------------------------
__device__ __nv_bfloat16 g_wd[(size_t)NI * DB * HH];   // merged down weights [n][d][h]
__device__ __nv_bfloat16 g_wu[(size_t)NI * HH * DB];   // merged up   weights [n][h][d]
__device__ float         g_bd[NI * DB];
__device__ float         g_bu[NI * HH];
__device__ __nv_bfloat16 g_y1[(size_t)NI * SQ * DB];   // relu(down(x)) bf16 [n][s][d]

// ---------------------------------------------------------------------------
// Helpers
// ---------------------------------------------------------------------------
#define DEVINL __device__ __forceinline__

DEVINL uint32_t smem_u32(const void* p) {
    uint32_t a;
    asm("{ .reg .u64 t; cvta.to.shared.u64 t, %1; cvt.u32.u64 %0, t; }" : "=r"(a) : "l"(p));
    return a;
}
DEVINL uint32_t packbf2(float lo, float hi) {
    uint32_t r;
    asm("cvt.rn.bf16x2.f32 %0, %1, %2;" : "=r"(r) : "f"(hi), "f"(lo));
    return r;
}

#define SW128(o) ((o) ^ (((o) >> 3) & 0x70))

DEVINL void ldsm4(uint32_t& r0, uint32_t& r1, uint32_t& r2, uint32_t& r3, uint32_t addr) {
    asm volatile("ldmatrix.sync.aligned.m8n8.x4.shared.b16 {%0,%1,%2,%3}, [%4];"
                 : "=r"(r0), "=r"(r1), "=r"(r2), "=r"(r3) : "r"(addr));
}
DEVINL void mma16816(float* d, const uint32_t* a, uint32_t b0, uint32_t b1) {
    asm volatile(
        "mma.sync.aligned.m16n8k16.row.col.f32.bf16.bf16.f32 "
        "{%0,%1,%2,%3}, {%4,%5,%6,%7}, {%8,%9}, {%0,%1,%2,%3};"
        : "+f"(d[0]), "+f"(d[1]), "+f"(d[2]), "+f"(d[3])
        : "r"(a[0]), "r"(a[1]), "r"(a[2]), "r"(a[3]), "r"(b0), "r"(b1));
}
DEVINL void cp16(uint32_t dst, const void* src) {
    asm volatile("cp.async.cg.shared.global [%0], [%1], 16;" :: "r"(dst), "l"(src));
}
#define CP_COMMIT() asm volatile("cp.async.commit_group;" ::: "memory")
template <int N> DEVINL void cp_wait() {
    asm volatile("cp.async.wait_group %0;" :: "n"(N) : "memory");
}

// ---------------------------------------------------------------------------
// SMEM layout (both GEMMs):
//   A stages 3x16KB [0,48K)   (gemm1 uses only slots 0,1)
//   B stages 3x16KB [48K,96K)
//   bias at 96K
// 98K/CTA -> 2 CTAs/SM (196K of 228K).
// ---------------------------------------------------------------------------
constexpr uint32_t STG_SZ   = 128 * 128;     // 16 KB per operand stage (128 rows x 64 bf16)
constexpr uint32_t OFF_B0   = 3 * STG_SZ;    // 48 KB
constexpr uint32_t OFF_BIAS = 6 * STG_SZ;    // 96 KB
constexpr uint32_t SMEM_TOTAL = 6 * STG_SZ + 2048;

// ---------------------------------------------------------------------------
// Weight / bias merge kernels
// ---------------------------------------------------------------------------
constexpr int E2 = DB * HH / 2;   // float2 elements per expert

__global__ void merge_wd_kernel(const float* __restrict__ w, const float* __restrict__ prob) {
    __shared__ float p[NI * KE];
    if (threadIdx.x < NI * KE) p[threadIdx.x] = prob[threadIdx.x];
    __syncthreads();
    int e2 = blockIdx.x * 256 + threadIdx.x;
    const float2* w2 = reinterpret_cast<const float2*>(w);
    float2 wv[KE];
#pragma unroll
    for (int k = 0; k < KE; ++k) wv[k] = w2[(size_t)k * E2 + e2];
    uint32_t* out = reinterpret_cast<uint32_t*>(g_wd);
#pragma unroll
    for (int n = 0; n < NI; ++n) {
        float x = 0.f, y = 0.f;
#pragma unroll
        for (int k = 0; k < KE; ++k) {
            x = fmaf(p[n * KE + k], wv[k].x, x);
            y = fmaf(p[n * KE + k], wv[k].y, y);
        }
        out[(size_t)n * E2 + e2] = packbf2(x, y);
    }
}

__global__ void merge_wu_kernel(const float* __restrict__ w, const float* __restrict__ prob) {
    __shared__ float p[NI * KE];
    if (threadIdx.x < NI * KE) p[threadIdx.x] = prob[threadIdx.x];
    __syncthreads();
    int e2 = blockIdx.x * 256 + threadIdx.x;
    const float2* w2 = reinterpret_cast<const float2*>(w);
    float2 wv[KE];
#pragma unroll
    for (int k = 0; k < KE; ++k) wv[k] = w2[(size_t)k * E2 + e2];
    uint32_t* out = reinterpret_cast<uint32_t*>(g_wu);
#pragma unroll
    for (int n = 0; n < NI; ++n) {
        float x = 0.f, y = 0.f;
#pragma unroll
        for (int k = 0; k < KE; ++k) {
            x = fmaf(p[n * KE + k], wv[k].x, x);
            y = fmaf(p[n * KE + k], wv[k].y, y);
        }
        out[(size_t)n * E2 + e2] = packbf2(x, y);
    }
}

__global__ void merge_b_kernel(const float* __restrict__ bd_in,
                               const float* __restrict__ bu_in,
                               const float* __restrict__ prob) {
    int g = blockIdx.x * 256 + threadIdx.x;
    if (g >= NI * (DB + HH)) return;
    int n = g / (DB + HH);
    int j = g % (DB + HH);
    float acc = 0.f;
    if (j < DB) {
#pragma unroll
        for (int k = 0; k < KE; ++k) acc = fmaf(prob[n * KE + k], bd_in[k * DB + j], acc);
        g_bd[n * DB + j] = acc;
    } else {
        int jj = j - DB;
#pragma unroll
        for (int k = 0; k < KE; ++k) acc = fmaf(prob[n * KE + k], bu_in[k * HH + jj], acc);
        g_bu[n * HH + jj] = acc;
    }
}

// ---------------------------------------------------------------------------
// Compute: CTA tile 128(m) x 128(n), 8 warps as 4m x 2n, warp tile 32 x 64.
// B fragments hoisted in pairs (2x ldsm.x4 then 8 HMMAs).
// ---------------------------------------------------------------------------
struct WarpId { int lane, wm, wn; };

DEVINL void compute_stage(uint32_t abase, uint32_t bbase, const WarpId& w,
                          float acc[2][8][4]) {
#pragma unroll
    for (int ks = 0; ks < 4; ++ks) {
        uint32_t a[2][4];
        {
            int r = w.wm * 32 + (w.lane & 15);
            uint32_t co = (uint32_t)(ks * 32 + ((w.lane >> 4) << 4));
            uint32_t o0 = (uint32_t)(r * 128) + co;
            uint32_t o1 = (uint32_t)((r + 16) * 128) + co;
            ldsm4(a[0][0], a[0][1], a[0][2], a[0][3], abase + SW128(o0));
            ldsm4(a[1][0], a[1][1], a[1][2], a[1][3], abase + SW128(o1));
        }
        int brb = w.wn * 64 + (w.lane & 7) + ((w.lane >> 4) & 1) * 8;
        uint32_t bco = (uint32_t)(ks * 32 + ((w.lane >> 3) & 1) * 16);
#pragma unroll
        for (int h = 0; h < 2; ++h) {
            uint32_t b[2][4];
#pragma unroll
            for (int g2 = 0; g2 < 2; ++g2) {
                int g = h * 2 + g2;
                ldsm4(b[g2][0], b[g2][1], b[g2][2], b[g2][3],
                      bbase + SW128((uint32_t)((brb + g * 16) * 128) + bco));
            }
#pragma unroll
            for (int g2 = 0; g2 < 2; ++g2) {
                int g = h * 2 + g2;
                mma16816(acc[0][2 * g],     a[0], b[g2][0], b[g2][1]);
                mma16816(acc[1][2 * g],     a[1], b[g2][0], b[g2][1]);
                mma16816(acc[0][2 * g + 1], a[0], b[g2][2], b[g2][3]);
                mma16816(acc[1][2 * g + 1], a[1], b[g2][2], b[g2][3]);
            }
        }
    }
}

// cp.async a 128-row x 64-col bf16 tile into `dst0` (swizzled)
DEVINL void cp_tile128(uint32_t dst0, const __nv_bfloat16* src, int ld, int kofs, int tid) {
#pragma unroll
    for (int i = 0; i < 4; ++i) {
        int idx = tid + i * 256;
        int row = idx >> 3, seg = idx & 7;
        uint32_t o = (uint32_t)(row * 128 + seg * 16);
        cp16(dst0 + SW128(o), src + (size_t)row * ld + kofs + seg * 8);
    }
}

// ---------------------------------------------------------------------------
// GEMM1: y1[n,s,d] = relu( x[n,s,:] . wd[n,d,:] + bd[n,d] )
// grid: n(16) x mt(16) x nt(2).
// Pipeline: B = 3-stage cp.async ring, cp_wait<1> (no drain);
//           A = LDG fp32 -> cvt -> STS double buffer, STS for chunk c+1
//           issued right after the barrier while computing chunk c.
// ---------------------------------------------------------------------------
__global__ __launch_bounds__(256, 2) void gemm1_kernel(const float* __restrict__ X) {
    extern __shared__ __align__(1024) char sm[];
    uint32_t sbase = smem_u32(sm);
    int tid = threadIdx.x;
    WarpId w{tid & 31, (tid >> 5) & 3, tid >> 7};

    int n  = blockIdx.x >> 5;
    int mt = (blockIdx.x >> 1) & 15;
    int nt = blockIdx.x & 1;

    const float* Xa = X + (size_t)(n * SQ + mt * 128) * HH;
    const __nv_bfloat16* Bw = g_wd + (size_t)n * DB * HH + (size_t)(nt * 128) * HH;
    float* bias_s = reinterpret_cast<float*>(sm + OFF_BIAS);
    if (tid < 128) bias_s[tid] = g_bd[n * DB + nt * 128 + tid];

    float acc[2][8][4];
#pragma unroll
    for (int i = 0; i < 2; ++i)
#pragma unroll
        for (int j = 0; j < 8; ++j)
#pragma unroll
            for (int k = 0; k < 4; ++k) acc[i][j][k] = 0.f;

    uint2 au[8];
    auto ldgA = [&](int c) {
#pragma unroll
        for (int i = 0; i < 8; ++i) {
            int idx = tid + i * 256;
            int row = idx >> 4, c4 = idx & 15;
            float4 v = *reinterpret_cast<const float4*>(Xa + (size_t)row * HH + c * 64 + c4 * 4);
            au[i].x = packbf2(v.x, v.y);
            au[i].y = packbf2(v.z, v.w);
        }
    };
    auto stsA = [&](int s) {
#pragma unroll
        for (int i = 0; i < 8; ++i) {
            int idx = tid + i * 256;
            int row = idx >> 4, c4 = idx & 15;
            uint32_t o = (uint32_t)(row * 128 + c4 * 8);
            *reinterpret_cast<uint2*>(sm + s * STG_SZ + SW128(o)) = au[i];
        }
    };

    constexpr int NC = HH / 64;   // 16

    // prologue: B0, B1 in flight; A0 in smem; A1 in registers
    cp_tile128(sbase + OFF_B0, Bw, HH, 0, tid);
    CP_COMMIT();
    cp_tile128(sbase + OFF_B0 + STG_SZ, Bw, HH, 64, tid);
    CP_COMMIT();
    ldgA(0);
    stsA(0);
    ldgA(1);

    for (int c = 0; c < NC; ++c) {
        if (c + 1 < NC) cp_wait<1>(); else cp_wait<0>();
        __syncthreads();
        if (c + 2 < NC) {
            cp_tile128(sbase + OFF_B0 + (uint32_t)((c + 2) % 3) * STG_SZ, Bw, HH, (c + 2) * 64, tid);
            CP_COMMIT();
        }
        if (c + 1 < NC) {
            stsA((c + 1) & 1);
            if (c + 2 < NC) ldgA(c + 2);
        }
        compute_stage(sbase + (uint32_t)(c & 1) * STG_SZ,
                      sbase + OFF_B0 + (uint32_t)(c % 3) * STG_SZ, w, acc);
    }

    // epilogue: bias + relu -> bf16, direct STG
    uint32_t* y1w = reinterpret_cast<uint32_t*>(g_y1 + (size_t)(n * SQ + mt * 128) * DB + nt * 128);
    int r0 = w.wm * 32 + (w.lane >> 2);
    int c0 = w.wn * 64 + (w.lane & 3) * 2;
#pragma unroll
    for (int mi = 0; mi < 2; ++mi)
#pragma unroll
        for (int ni = 0; ni < 8; ++ni) {
            int r = r0 + mi * 16;
            int col = c0 + ni * 8;
            float b0 = bias_s[col], b1 = bias_s[col + 1];
            uint32_t p0 = packbf2(fmaxf(acc[mi][ni][0] + b0, 0.f),
                                  fmaxf(acc[mi][ni][1] + b1, 0.f));
            uint32_t p1 = packbf2(fmaxf(acc[mi][ni][2] + b0, 0.f),
                                  fmaxf(acc[mi][ni][3] + b1, 0.f));
            y1w[(size_t)r * (DB / 2) + col / 2]       = p0;
            y1w[(size_t)(r + 8) * (DB / 2) + col / 2] = p1;
        }
}

// ---------------------------------------------------------------------------
// GEMM2: out[n,s,h] = x[n,s,h] + y1[n,s,:] . wu[n,h,:] + bu[n,h]
// grid: n(16) x mt(16) x nt(8).
// Pipeline: A and B both 3-stage cp.async rings, one commit-group per chunk,
// cp_wait<1> (no drain).
// ---------------------------------------------------------------------------
__global__ __launch_bounds__(256, 2) void gemm2_kernel(const float* __restrict__ X,
                                                       float* __restrict__ Out) {
    extern __shared__ __align__(1024) char sm[];
    uint32_t sbase = smem_u32(sm);
    int tid = threadIdx.x;
    WarpId w{tid & 31, (tid >> 5) & 3, tid >> 7};

    int n  = blockIdx.x >> 7;
    int mt = (blockIdx.x >> 3) & 15;
    int nt = blockIdx.x & 7;

    const __nv_bfloat16* Aa = g_y1 + (size_t)(n * SQ + mt * 128) * DB;
    const __nv_bfloat16* Bw = g_wu + (size_t)(n * HH + nt * 128) * DB;
    float* bias_s = reinterpret_cast<float*>(sm + OFF_BIAS);
    if (tid < 128) bias_s[tid] = g_bu[n * HH + nt * 128 + tid];

    float acc[2][8][4];
#pragma unroll
    for (int i = 0; i < 2; ++i)
#pragma unroll
        for (int j = 0; j < 8; ++j)
#pragma unroll
            for (int k = 0; k < 4; ++k) acc[i][j][k] = 0.f;

    constexpr int NC = DB / 64;   // 4

    // prologue: chunks 0,1 in flight
    cp_tile128(sbase,                    Aa, DB, 0, tid);
    cp_tile128(sbase + OFF_B0,           Bw, DB, 0, tid);
    CP_COMMIT();
    cp_tile128(sbase + STG_SZ,           Aa, DB, 64, tid);
    cp_tile128(sbase + OFF_B0 + STG_SZ,  Bw, DB, 64, tid);
    CP_COMMIT();

    for (int c = 0; c < NC; ++c) {
        if (c + 1 < NC) cp_wait<1>(); else cp_wait<0>();
        __syncthreads();
        if (c + 2 < NC) {
            uint32_t s2 = (uint32_t)((c + 2) % 3) * STG_SZ;
            cp_tile128(sbase + s2,          Aa, DB, (c + 2) * 64, tid);
            cp_tile128(sbase + OFF_B0 + s2, Bw, DB, (c + 2) * 64, tid);
            CP_COMMIT();
        }
        compute_stage(sbase + (uint32_t)(c % 3) * STG_SZ,
                      sbase + OFF_B0 + (uint32_t)(c % 3) * STG_SZ, w, acc);
    }

    // epilogue: bias + residual, direct fp32 STG (float2 per lane)
    size_t rowbase = (size_t)(n * SQ + mt * 128);
    int r0 = w.wm * 32 + (w.lane >> 2);
    int c0 = w.wn * 64 + (w.lane & 3) * 2;
#pragma unroll
    for (int mi = 0; mi < 2; ++mi)
#pragma unroll
        for (int ni = 0; ni < 8; ++ni) {
            int r = r0 + mi * 16;
            int col = c0 + ni * 8;
            float b0 = bias_s[col], b1 = bias_s[col + 1];
            size_t g0 = (rowbase + r) * HH + nt * 128 + col;
            size_t g1 = g0 + (size_t)8 * HH;
            float2 xv0 = *reinterpret_cast<const float2*>(X + g0);
            float2 xv1 = *reinterpret_cast<const float2*>(X + g1);
            float2 o0, o1;
            o0.x = acc[mi][ni][0] + b0 + xv0.x;
            o0.y = acc[mi][ni][1] + b1 + xv0.y;
            o1.x = acc[mi][ni][2] + b0 + xv1.x;
            o1.y = acc[mi][ni][3] + b1 + xv1.y;
            *reinterpret_cast<float2*>(Out + g0) = o0;
            *reinterpret_cast<float2*>(Out + g1) = o1;
        }
}

// ---------------------------------------------------------------------------
// Launch
// ---------------------------------------------------------------------------
extern "C" void kernel_launch(void* const* d_in, const int* in_sizes, int n_in,
                              void* d_out, int out_size) {
    const float* X    = (const float*)d_in[0];
    const float* prob = (const float*)d_in[1];
    const float* wd   = (const float*)d_in[2];
    const float* bd   = (const float*)d_in[3];
    const float* wu   = (const float*)d_in[4];
    const float* bu   = (const float*)d_in[5];
    float* out = (float*)d_out;

    cudaFuncSetAttribute(gemm1_kernel, cudaFuncAttributeMaxDynamicSharedMemorySize, SMEM_TOTAL);
    cudaFuncSetAttribute(gemm2_kernel, cudaFuncAttributeMaxDynamicSharedMemorySize, SMEM_TOTAL);

    merge_wd_kernel<<<E2 / 256, 256>>>(wd, prob);
    merge_wu_kernel<<<E2 / 256, 256>>>(wu, prob);
    merge_b_kernel<<<(NI * (DB + HH) + 255) / 256, 256>>>(bd, bu, prob);

    gemm1_kernel<<<NI * 16 * 2, 256, SMEM_TOTAL>>>(X);
    gemm2_kernel<<<NI * 16 * 8, 256, SMEM_TOTAL>>>(X, out);
}

// round 15
// speedup vs baseline: 1.3087x; 1.3087x over previous
#include <cuda_runtime.h>
#include <cuda_bf16.h>
#include <cstdint>
#include <cstddef>

// ---------------------------------------------------------------------------
// Problem sizes
// ---------------------------------------------------------------------------
constexpr int NI = 16;      // instances
constexpr int SQ = 2048;    // sequence
constexpr int HH = 1024;    // hidden
constexpr int KE = 8;       // experts
constexpr int DB = 256;     // bottleneck

// ---------------------------------------------------------------------------
// Device scratch (static globals -- no allocations allowed)
// ---------------------------------------------------------------------------
__device__ __nv_bfloat16 g_wd[(size_t)NI * DB * HH];   // merged down weights [n][d][h]
__device__ __nv_bfloat16 g_wu[(size_t)NI * HH * DB];   // merged up   weights [n][h][d]
__device__ float         g_bd[NI * DB];
__device__ float         g_bu[NI * HH];
__device__ __nv_bfloat16 g_y1[(size_t)NI * SQ * DB];   // relu(down(x)) bf16 [n][s][d]

// ---------------------------------------------------------------------------
// Helpers
// ---------------------------------------------------------------------------
#define DEVINL __device__ __forceinline__

DEVINL uint32_t smem_u32(const void* p) {
    uint32_t a;
    asm("{ .reg .u64 t; cvta.to.shared.u64 t, %1; cvt.u32.u64 %0, t; }" : "=r"(a) : "l"(p));
    return a;
}
DEVINL uint32_t packbf2(float lo, float hi) {
    uint32_t r;
    asm("cvt.rn.bf16x2.f32 %0, %1, %2;" : "=r"(r) : "f"(hi), "f"(lo));
    return r;
}

#define SW128(o) ((o) ^ (((o) >> 3) & 0x70))

DEVINL void ldsm4(uint32_t& r0, uint32_t& r1, uint32_t& r2, uint32_t& r3, uint32_t addr) {
    asm volatile("ldmatrix.sync.aligned.m8n8.x4.shared.b16 {%0,%1,%2,%3}, [%4];"
                 : "=r"(r0), "=r"(r1), "=r"(r2), "=r"(r3) : "r"(addr));
}
DEVINL void mma16816(float* d, const uint32_t* a, uint32_t b0, uint32_t b1) {
    asm volatile(
        "mma.sync.aligned.m16n8k16.row.col.f32.bf16.bf16.f32 "
        "{%0,%1,%2,%3}, {%4,%5,%6,%7}, {%8,%9}, {%0,%1,%2,%3};"
        : "+f"(d[0]), "+f"(d[1]), "+f"(d[2]), "+f"(d[3])
        : "r"(a[0]), "r"(a[1]), "r"(a[2]), "r"(a[3]), "r"(b0), "r"(b1));
}
DEVINL void cp16(uint32_t dst, const void* src) {
    asm volatile("cp.async.cg.shared.global [%0], [%1], 16;" :: "r"(dst), "l"(src));
}
#define CP_COMMIT() asm volatile("cp.async.commit_group;" ::: "memory")
template <int N> DEVINL void cp_wait() {
    asm volatile("cp.async.wait_group %0;" :: "n"(N) : "memory");
}
DEVINL void l2_prefetch(const void* p) {
    asm volatile("prefetch.global.L2 [%0];" :: "l"(p));
}

// ---------------------------------------------------------------------------
// SMEM layout (both GEMMs): A stages 2x16KB [0,32K) | B stages 2x16KB [32K,64K)
// bias at 64K.  Total 66K/CTA -> 2 CTAs/SM (132K of 228K).
// ---------------------------------------------------------------------------
constexpr uint32_t STG_SZ   = 128 * 128;     // 16 KB per operand stage (128 rows x 64 bf16)
constexpr uint32_t OFF_B0   = 2 * STG_SZ;    // 32 KB
constexpr uint32_t OFF_BIAS = 64 * 1024;
constexpr uint32_t SMEM_TOTAL = 66 * 1024;

// ---------------------------------------------------------------------------
// Fused weight/bias merge (one launch):
//   blocks [0,512)      -> wd merge
//   blocks [512,1024)   -> wu merge
//   blocks [1024,1104)  -> biases
// ---------------------------------------------------------------------------
constexpr int E2 = DB * HH / 2;            // 131072 float2 per expert
constexpr int WBLK = E2 / 256;             // 512 blocks per weight tensor
constexpr int BBLK = (NI * (DB + HH) + 255) / 256;   // 80 blocks for biases

__global__ void merge_all_kernel(const float* __restrict__ wd_in,
                                 const float* __restrict__ wu_in,
                                 const float* __restrict__ bd_in,
                                 const float* __restrict__ bu_in,
                                 const float* __restrict__ prob) {
    __shared__ float p[NI * KE];
    int bid = blockIdx.x;
    if (bid < 2 * WBLK) {
        if (threadIdx.x < NI * KE) p[threadIdx.x] = prob[threadIdx.x];
        __syncthreads();
        bool is_wu = bid >= WBLK;
        int e2 = (is_wu ? bid - WBLK : bid) * 256 + threadIdx.x;
        const float2* w2 = reinterpret_cast<const float2*>(is_wu ? wu_in : wd_in);
        uint32_t* out = reinterpret_cast<uint32_t*>(is_wu ? g_wu : g_wd);
        float2 wv[KE];
#pragma unroll
        for (int k = 0; k < KE; ++k) wv[k] = w2[(size_t)k * E2 + e2];
#pragma unroll
        for (int n = 0; n < NI; ++n) {
            float x = 0.f, y = 0.f;
#pragma unroll
            for (int k = 0; k < KE; ++k) {
                x = fmaf(p[n * KE + k], wv[k].x, x);
                y = fmaf(p[n * KE + k], wv[k].y, y);
            }
            out[(size_t)n * E2 + e2] = packbf2(x, y);
        }
    } else {
        int g = (bid - 2 * WBLK) * 256 + threadIdx.x;
        if (g >= NI * (DB + HH)) return;
        int n = g / (DB + HH);
        int j = g % (DB + HH);
        float acc = 0.f;
        if (j < DB) {
#pragma unroll
            for (int k = 0; k < KE; ++k) acc = fmaf(prob[n * KE + k], bd_in[k * DB + j], acc);
            g_bd[n * DB + j] = acc;
        } else {
            int jj = j - DB;
#pragma unroll
            for (int k = 0; k < KE; ++k) acc = fmaf(prob[n * KE + k], bu_in[k * HH + jj], acc);
            g_bu[n * HH + jj] = acc;
        }
    }
}

// ---------------------------------------------------------------------------
// Compute: CTA tile 128(m) x 128(n), 8 warps as 4m x 2n, warp tile 32 x 64.
// B fragments hoisted in pairs (2x ldsm.x4 then 8 HMMAs).
// ---------------------------------------------------------------------------
struct WarpId { int lane, wm, wn; };

DEVINL void compute_stage(uint32_t abase, uint32_t bbase, const WarpId& w,
                          float acc[2][8][4]) {
#pragma unroll
    for (int ks = 0; ks < 4; ++ks) {
        uint32_t a[2][4];
        {
            int r = w.wm * 32 + (w.lane & 15);
            uint32_t co = (uint32_t)(ks * 32 + ((w.lane >> 4) << 4));
            uint32_t o0 = (uint32_t)(r * 128) + co;
            uint32_t o1 = (uint32_t)((r + 16) * 128) + co;
            ldsm4(a[0][0], a[0][1], a[0][2], a[0][3], abase + SW128(o0));
            ldsm4(a[1][0], a[1][1], a[1][2], a[1][3], abase + SW128(o1));
        }
        int brb = w.wn * 64 + (w.lane & 7) + ((w.lane >> 4) & 1) * 8;
        uint32_t bco = (uint32_t)(ks * 32 + ((w.lane >> 3) & 1) * 16);
#pragma unroll
        for (int h = 0; h < 2; ++h) {
            uint32_t b[2][4];
#pragma unroll
            for (int g2 = 0; g2 < 2; ++g2) {
                int g = h * 2 + g2;
                ldsm4(b[g2][0], b[g2][1], b[g2][2], b[g2][3],
                      bbase + SW128((uint32_t)((brb + g * 16) * 128) + bco));
            }
#pragma unroll
            for (int g2 = 0; g2 < 2; ++g2) {
                int g = h * 2 + g2;
                mma16816(acc[0][2 * g],     a[0], b[g2][0], b[g2][1]);
                mma16816(acc[1][2 * g],     a[1], b[g2][0], b[g2][1]);
                mma16816(acc[0][2 * g + 1], a[0], b[g2][2], b[g2][3]);
                mma16816(acc[1][2 * g + 1], a[1], b[g2][2], b[g2][3]);
            }
        }
    }
}

// cp.async a 128-row x 64-col bf16 tile into `dst0` (swizzled)
DEVINL void cp_tile128(uint32_t dst0, const __nv_bfloat16* src, int ld, int kofs, int tid) {
#pragma unroll
    for (int i = 0; i < 4; ++i) {
        int idx = tid + i * 256;
        int row = idx >> 3, seg = idx & 7;
        uint32_t o = (uint32_t)(row * 128 + seg * 16);
        cp16(dst0 + SW128(o), src + (size_t)row * ld + kofs + seg * 8);
    }
}

// ---------------------------------------------------------------------------
// GEMM1: y1[n,s,d] = relu( x[n,s,:] . wd[n,d,:] + bd[n,d] )
// grid: n(16) x mt(16) x nt(2), nt innermost so X tile hits L2 on 2nd read.
// ---------------------------------------------------------------------------
__global__ __launch_bounds__(256, 2) void gemm1_kernel(const float* __restrict__ X) {
    extern __shared__ __align__(1024) char sm[];
    uint32_t sbase = smem_u32(sm);
    int tid = threadIdx.x;
    WarpId w{tid & 31, (tid >> 5) & 3, tid >> 7};

    int n  = blockIdx.x >> 5;
    int mt = (blockIdx.x >> 1) & 15;
    int nt = blockIdx.x & 1;

    const float* Xa = X + (size_t)(n * SQ + mt * 128) * HH;
    const __nv_bfloat16* Bw = g_wd + (size_t)n * DB * HH + (size_t)(nt * 128) * HH;
    float* bias_s = reinterpret_cast<float*>(sm + OFF_BIAS);
    if (tid < 128) bias_s[tid] = g_bd[n * DB + nt * 128 + tid];

    float acc[2][8][4];
#pragma unroll
    for (int i = 0; i < 2; ++i)
#pragma unroll
        for (int j = 0; j < 8; ++j)
#pragma unroll
            for (int k = 0; k < 4; ++k) acc[i][j][k] = 0.f;

    uint2 au[8];
    auto ldgA = [&](int c) {
#pragma unroll
        for (int i = 0; i < 8; ++i) {
            int idx = tid + i * 256;
            int row = idx >> 4, c4 = idx & 15;
            float4 v = *reinterpret_cast<const float4*>(Xa + (size_t)row * HH + c * 64 + c4 * 4);
            au[i].x = packbf2(v.x, v.y);
            au[i].y = packbf2(v.z, v.w);
        }
    };
    auto stsA = [&](int s) {
#pragma unroll
        for (int i = 0; i < 8; ++i) {
            int idx = tid + i * 256;
            int row = idx >> 4, c4 = idx & 15;
            uint32_t o = (uint32_t)(row * 128 + c4 * 8);
            *reinterpret_cast<uint2*>(sm + s * STG_SZ + SW128(o)) = au[i];
        }
    };

    // prologue: stage 0
    ldgA(0);
    cp_tile128(sbase + OFF_B0, Bw, HH, 0, tid);
    CP_COMMIT();
    stsA(0);
    cp_wait<0>();
    __syncthreads();

    constexpr int NC = HH / 64;   // 16
    for (int c = 0; c < NC; ++c) {
        int s = c & 1;
        if (c + 1 < NC) {
            ldgA(c + 1);
            cp_tile128(sbase + OFF_B0 + (uint32_t)((c + 1) & 1) * STG_SZ, Bw, HH, (c + 1) * 64, tid);
            CP_COMMIT();
        }
        compute_stage(sbase + (uint32_t)s * STG_SZ,
                      sbase + OFF_B0 + (uint32_t)s * STG_SZ, w, acc);
        if (c + 1 < NC) {
            stsA((c + 1) & 1);
            cp_wait<0>();
        }
        __syncthreads();
    }

    // epilogue: bias + relu -> bf16, direct STG
    uint32_t* y1w = reinterpret_cast<uint32_t*>(g_y1 + (size_t)(n * SQ + mt * 128) * DB + nt * 128);
    int r0 = w.wm * 32 + (w.lane >> 2);
    int c0 = w.wn * 64 + (w.lane & 3) * 2;
#pragma unroll
    for (int mi = 0; mi < 2; ++mi)
#pragma unroll
        for (int ni = 0; ni < 8; ++ni) {
            int r = r0 + mi * 16;
            int col = c0 + ni * 8;
            float b0 = bias_s[col], b1 = bias_s[col + 1];
            uint32_t p0 = packbf2(fmaxf(acc[mi][ni][0] + b0, 0.f),
                                  fmaxf(acc[mi][ni][1] + b1, 0.f));
            uint32_t p1 = packbf2(fmaxf(acc[mi][ni][2] + b0, 0.f),
                                  fmaxf(acc[mi][ni][3] + b1, 0.f));
            y1w[(size_t)r * (DB / 2) + col / 2]       = p0;
            y1w[(size_t)(r + 8) * (DB / 2) + col / 2] = p1;
        }
}

// ---------------------------------------------------------------------------
// GEMM2: out[n,s,h] = x[n,s,h] + y1[n,s,:] . wu[n,h,:] + bu[n,h]
// grid: n(16) x mt(16) x nt(8), nt innermost so y1 tile hits L2 on re-reads.
// X residual tile is L2-prefetched in the prologue so the epilogue loads hit
// L2 (~250cyc) instead of DRAM (~600cyc).
// ---------------------------------------------------------------------------
__global__ __launch_bounds__(256, 2) void gemm2_kernel(const float* __restrict__ X,
                                                       float* __restrict__ Out) {
    extern __shared__ __align__(1024) char sm[];
    uint32_t sbase = smem_u32(sm);
    int tid = threadIdx.x;
    WarpId w{tid & 31, (tid >> 5) & 3, tid >> 7};

    int n  = blockIdx.x >> 7;
    int mt = (blockIdx.x >> 3) & 15;
    int nt = blockIdx.x & 7;

    const __nv_bfloat16* Aa = g_y1 + (size_t)(n * SQ + mt * 128) * DB;
    const __nv_bfloat16* Bw = g_wu + (size_t)(n * HH + nt * 128) * DB;
    float* bias_s = reinterpret_cast<float*>(sm + OFF_BIAS);
    if (tid < 128) bias_s[tid] = g_bu[n * HH + nt * 128 + tid];

    float acc[2][8][4];
#pragma unroll
    for (int i = 0; i < 2; ++i)
#pragma unroll
        for (int j = 0; j < 8; ++j)
#pragma unroll
            for (int k = 0; k < 4; ++k) acc[i][j][k] = 0.f;

    cp_tile128(sbase, Aa, DB, 0, tid);
    cp_tile128(sbase + OFF_B0, Bw, DB, 0, tid);
    CP_COMMIT();

    // L2 prefetch of this CTA's X residual tile: 128 rows x 512B (4x128B lines)
    {
        const float* Xp = X + (size_t)(n * SQ + mt * 128) * HH + nt * 128;
#pragma unroll
        for (int i = 0; i < 2; ++i) {
            int idx = tid + i * 256;
            int row = idx >> 2, seg = idx & 3;
            l2_prefetch(Xp + (size_t)row * HH + seg * 32);
        }
    }

    constexpr int NC = DB / 64;   // 4
    for (int c = 0; c < NC; ++c) {
        if (c + 1 < NC) {
            cp_tile128(sbase + (uint32_t)((c + 1) & 1) * STG_SZ, Aa, DB, (c + 1) * 64, tid);
            cp_tile128(sbase + OFF_B0 + (uint32_t)((c + 1) & 1) * STG_SZ, Bw, DB, (c + 1) * 64, tid);
            CP_COMMIT();
            cp_wait<1>();
        } else {
            cp_wait<0>();
        }
        __syncthreads();
        compute_stage(sbase + (uint32_t)(c & 1) * STG_SZ,
                      sbase + OFF_B0 + (uint32_t)(c & 1) * STG_SZ, w, acc);
        __syncthreads();
    }

    // epilogue: bias + residual, direct fp32 STG (float2 per lane)
    size_t rowbase = (size_t)(n * SQ + mt * 128);
    int r0 = w.wm * 32 + (w.lane >> 2);
    int c0 = w.wn * 64 + (w.lane & 3) * 2;
#pragma unroll
    for (int mi = 0; mi < 2; ++mi)
#pragma unroll
        for (int ni = 0; ni < 8; ++ni) {
            int r = r0 + mi * 16;
            int col = c0 + ni * 8;
            float b0 = bias_s[col], b1 = bias_s[col + 1];
            size_t g0 = (rowbase + r) * HH + nt * 128 + col;
            size_t g1 = g0 + (size_t)8 * HH;
            float2 xv0 = *reinterpret_cast<const float2*>(X + g0);
            float2 xv1 = *reinterpret_cast<const float2*>(X + g1);
            float2 o0, o1;
            o0.x = acc[mi][ni][0] + b0 + xv0.x;
            o0.y = acc[mi][ni][1] + b1 + xv0.y;
            o1.x = acc[mi][ni][2] + b0 + xv1.x;
            o1.y = acc[mi][ni][3] + b1 + xv1.y;
            *reinterpret_cast<float2*>(Out + g0) = o0;
            *reinterpret_cast<float2*>(Out + g1) = o1;
        }
}

// ---------------------------------------------------------------------------
// Launch
// ---------------------------------------------------------------------------
extern "C" void kernel_launch(void* const* d_in, const int* in_sizes, int n_in,
                              void* d_out, int out_size) {
    const float* X    = (const float*)d_in[0];
    const float* prob = (const float*)d_in[1];
    const float* wd   = (const float*)d_in[2];
    const float* bd   = (const float*)d_in[3];
    const float* wu   = (const float*)d_in[4];
    const float* bu   = (const float*)d_in[5];
    float* out = (float*)d_out;

    cudaFuncSetAttribute(gemm1_kernel, cudaFuncAttributeMaxDynamicSharedMemorySize, SMEM_TOTAL);
    cudaFuncSetAttribute(gemm2_kernel, cudaFuncAttributeMaxDynamicSharedMemorySize, SMEM_TOTAL);

    merge_all_kernel<<<2 * WBLK + BBLK, 256>>>(wd, wu, bd, bu, prob);

    gemm1_kernel<<<NI * 16 * 2, 256, SMEM_TOTAL>>>(X);
    gemm2_kernel<<<NI * 16 * 8, 256, SMEM_TOTAL>>>(X, out);
}